// round 16
// baseline (speedup 1.0000x reference)
#include <cuda_runtime.h>
#include <cuda_bf16.h>
#include <math.h>
#include <stdint.h>

// Problem constants
#define SQ   2048
#define HID  1024
#define DH   64
#define NHB  16
#define BHSD (NHB*SQ*DH)
#define LOG2E 1.4426950408889634f

// ---------------- scratch (static device memory; no allocation) ----------------
__device__ float g_V   [BHSD];
__device__ float g_LV  [BHSD];
__device__ float g_LQ  [BHSD];
__device__ float g_LK1 [BHSD];
__device__ float g_Mm  [NHB*64*64];
__device__ float g_bsum[512];
// packed bf16 hi/lo pairs (.x = hi pair, .y = lo pair), PERMUTED within 8-pair groups
__device__ __align__(16) uint2 g_Qp [32*SQ*(DH/2)];   // [plane][s][dpair'] (planes 0-15 used)
__device__ __align__(16) uint2 g_Kp [32*SQ*(DH/2)];   // [plane][s][dpair']
__device__ __align__(16) uint2 g_Vtp[32*DH*(SQ/2)];   // [plane][d][spair']
__device__ __align__(16) uint2 g_Xp [4096*512];       // [m][kpair']
__device__ __align__(16) uint2 g_Wtp[7*512*512];      // [pz][n][kpair']

struct ProjW {
    const float* w[7];   // w[6] = wlv1
    const float* b[7];   // b[6] = blv1
    const float* w2;     // wlv2
    const float* b2;     // blv2
};

// ---------------- helpers ----------------
__device__ __forceinline__ void mma16(float c[4], const uint32_t a[4],
                                      uint32_t b0, uint32_t b1) {
    asm volatile(
        "mma.sync.aligned.m16n8k16.row.col.f32.bf16.bf16.f32 "
        "{%0,%1,%2,%3}, {%4,%5,%6,%7}, {%8,%9}, {%0,%1,%2,%3};"
        : "+f"(c[0]), "+f"(c[1]), "+f"(c[2]), "+f"(c[3])
        : "r"(a[0]), "r"(a[1]), "r"(a[2]), "r"(a[3]), "r"(b0), "r"(b1));
}
__device__ __forceinline__ void cp16(uint32_t dst, const void* src) {
    asm volatile("cp.async.cg.shared.global [%0], [%1], 16;\n" :: "r"(dst), "l"(src));
}
__device__ __forceinline__ uint32_t pk2(__nv_bfloat16 a, __nv_bfloat16 b) {
    uint16_t xa = *reinterpret_cast<uint16_t*>(&a);
    uint16_t xb = *reinterpret_cast<uint16_t*>(&b);
    return (uint32_t)xa | ((uint32_t)xb << 16);
}
__device__ __forceinline__ uint2 pk_pair(float v0, float v1) {
    __nv_bfloat16 h0 = __float2bfloat16_rn(v0), h1 = __float2bfloat16_rn(v1);
    float l0 = v0 - __bfloat162float(h0), l1 = v1 - __bfloat162float(h1);
    return make_uint2(pk2(h0, h1),
                      pk2(__float2bfloat16_rn(l0), __float2bfloat16_rn(l1)));
}
// fragment permutation: within each 8-pair group, pair c stored at 2*(c&3)+(c>>2)
__device__ __forceinline__ int pidx(int p) {
    return (p & ~7) | ((p & 3) << 1) | ((p >> 2) & 1);
}
__device__ __forceinline__ float ex2(float x) {
    float r; asm("ex2.approx.ftz.f32 %0, %1;" : "=f"(r) : "f"(x));
    return r;
}

// ---------------- kernel 1: prep = split_x + split_w(+wlv sum) + bias sum ----------------
__global__ __launch_bounds__(256) void prep_kernel(const float* __restrict__ X, ProjW pw) {
    const int bid = blockIdx.x;
    const int tid = threadIdx.x;
    if (bid < 1024) {
        #pragma unroll
        for (int t = 0; t < 8; t++) {
            int idx = bid*2048 + t*256 + tid;
            float2 v = *(const float2*)&X[(size_t)idx * 2];
            g_Xp[(idx & ~7) | ((idx & 3) << 1) | ((idx >> 2) & 1)] = pk_pair(v.x, v.y);
        }
    } else if (bid < 1920) {
        int b2 = bid - 1024;
        int pz  = b2 >> 7;
        int rem = b2 & 127;
        int n0 = (rem >> 4) * 64;
        int k0 = (rem & 15) * 64;
        __shared__ float T[64][65];
        const float* W  = pw.w[pz];
        const float* W2 = pw.w2;
        #pragma unroll
        for (int t = 0; t < 16; t++) {
            int idx = tid + 256*t;
            int kk = idx >> 6, nn = idx & 63;
            float v = W[(size_t)(k0 + kk) * 512 + n0 + nn];
            if (pz == 6) v += W2[(size_t)(k0 + kk) * 512 + n0 + nn];
            T[kk][nn] = v;
        }
        __syncthreads();
        #pragma unroll
        for (int t = 0; t < 8; t++) {
            int idx = tid + 256*t;
            int nn = idx >> 5, kp = idx & 31;
            g_Wtp[((size_t)pz * 512 + n0 + nn) * 512 + (k0 >> 1) + pidx(kp)] =
                pk_pair(T[2*kp][nn], T[2*kp + 1][nn]);
        }
    } else {
        g_bsum[2*tid]     = pw.b[6][2*tid]     + pw.b2[2*tid];
        g_bsum[2*tid + 1] = pw.b[6][2*tid + 1] + pw.b2[2*tid + 1];
    }
}

// ---------------- kernel 2: projection GEMM, depth-3 pipeline, swizzled smem ----------------
// (A and B both read from swizzled smem with the same slot transform -> chunks stay matched)
__global__ __launch_bounds__(256, 2) void proj_bf(ProjW args) {
    extern __shared__ uint4 psm4[];    // 3 stages x (X 1024 + W 512) uint4

    const int pz = blockIdx.z;
    const int n0 = blockIdx.x * 64;
    const int m0 = blockIdx.y * 128;
    const float* __restrict__ Bv = (pz == 6) ? g_bsum : args.b[pz];

    const uint2* __restrict__ Xp  = g_Xp + (size_t)m0 * 512;
    const uint2* __restrict__ Wtp = g_Wtp + ((size_t)pz * 512 + n0) * 512;

    const int tid  = threadIdx.x;
    const int lane = tid & 31;
    const int g    = lane >> 2;
    const int tg   = lane & 3;
    const int r0   = 16 * (tid >> 5);
    const int gx   = g & 1;

    const uint32_t sb = (uint32_t)__cvta_generic_to_shared(psm4);

    auto stage = [&](int kt) {
        int buf = kt % 3;
        uint32_t xb = sb + (uint32_t)buf * (1536u * 16u);
        uint32_t wb = xb + 1024u * 16u;
        #pragma unroll
        for (int t = 0; t < 4; t++) {
            int idx = tid + 256*t;          // 0..1023
            int r = idx >> 3, c = idx & 7;
            int sl = c ^ ((r & 1) << 2);
            cp16(xb + (uint32_t)(r*8 + sl)*16u, Xp + (size_t)r*512 + kt*16 + 2*c);
        }
        #pragma unroll
        for (int t = 0; t < 2; t++) {
            int idx = tid + 256*t;          // 0..511
            int r = idx >> 3, c = idx & 7;
            int sl = c ^ ((r & 1) << 2);
            cp16(wb + (uint32_t)(r*8 + sl)*16u, Wtp + (size_t)r*512 + kt*16 + 2*c);
        }
        asm volatile("cp.async.commit_group;\n");
    };

    float acc[8][4];
    #pragma unroll
    for (int n = 0; n < 8; n++)
        #pragma unroll
        for (int q = 0; q < 4; q++) acc[n][q] = 0.f;

    stage(0); stage(1);

    for (int kt = 0; kt < 32; kt++) {
        if (kt < 31) asm volatile("cp.async.wait_group 1;\n");
        else         asm volatile("cp.async.wait_group 0;\n");
        __syncthreads();
        if (kt + 2 < 32) stage(kt + 2);

        const uint4* Xs = psm4 + (kt % 3) * 1536;
        const uint4* Ws = Xs + 1024;

        #pragma unroll
        for (int kk = 0; kk < 2; kk++) {
            int kx = kk ^ gx;   // slot index; both A and B fetched via kx -> logical chunks match
            uint4 u0 = Xs[(r0 + g    ) * 8 + 4*kx + tg];
            uint4 u1 = Xs[(r0 + g + 8) * 8 + 4*kx + tg];
            uint32_t ah[4] = {u0.x, u1.x, u0.z, u1.z};
            uint32_t al[4] = {u0.y, u1.y, u0.w, u1.w};
            #pragma unroll
            for (int n = 0; n < 8; n++) {
                uint4 B = Ws[(8*n + g) * 8 + 4*kx + tg];
                mma16(acc[n], ah, B.x, B.z);
                mma16(acc[n], ah, B.y, B.w);
                mma16(acc[n], al, B.x, B.z);
            }
        }
    }

    // epilogue: bias + scatter
    const int hh = n0 >> 6;
    #pragma unroll
    for (int n = 0; n < 8; n++) {
        int col = 8*n + 2*tg;           // even, 0..63 within head
        float b0 = Bv[n0 + col], b1 = Bv[n0 + col + 1];
        #pragma unroll
        for (int half = 0; half < 2; half++) {
            int m = m0 + r0 + g + 8*half;
            int bb = m >> 11, s = m & 2047;
            float v0 = acc[n][2*half + 0] + b0;
            float v1 = acc[n][2*half + 1] + b1;
            int cidx = bb*8 + hh;
            int pp = pidx(col >> 1);
            if (pz == 0) {
                g_Qp[((size_t)cidx * SQ + s) * (DH/2) + pp] =
                    pk_pair(v0 * (0.125f*LOG2E), v1 * (0.125f*LOG2E));
            } else if (pz == 1) {
                g_Kp[((size_t)cidx * SQ + s) * (DH/2) + pp] = pk_pair(v0, v1);
            } else if (pz == 5) {
                g_Kp[((size_t)(16 + cidx) * SQ + s) * (DH/2) + pp] = pk_pair(v0, v1);
            } else {
                float* Out = (pz == 2) ? g_V : (pz == 3) ? g_LQ
                           : (pz == 4) ? g_LK1 : g_LV;
                *(float2*)&Out[((size_t)cidx * SQ + s) * DH + col] = make_float2(v0, v1);
            }
        }
    }
}

// ---------------- kernel 3: aux = gram (blocks 0-15) + vtrans (blocks 16-1039) ----------------
__global__ __launch_bounds__(256) void aux_kernel() {
    __shared__ float T[64][65];
    const int tid = threadIdx.x;
    const int bid = blockIdx.x;

    if (bid < 16) {
        const int bh = bid;
        const float* __restrict__ P = g_LK1 + (size_t)bh * SQ * DH;
        const int ty = tid >> 4, tx = tid & 15;
        float acc[4][4];
        #pragma unroll
        for (int i = 0; i < 4; i++)
            #pragma unroll
            for (int j = 0; j < 4; j++) acc[i][j] = 0.f;
        for (int s0 = 0; s0 < SQ; s0 += 32) {
            #pragma unroll
            for (int t = 0; t < 2; t++) {
                int idx = tid + t * 256;
                int r = idx >> 4, c = idx & 15;
                float4 v = *(const float4*)&P[(size_t)(s0 + r) * DH + 4*c];
                T[r][4*c+0] = v.x; T[r][4*c+1] = v.y; T[r][4*c+2] = v.z; T[r][4*c+3] = v.w;
            }
            __syncthreads();
            #pragma unroll 8
            for (int ss = 0; ss < 32; ss++) {
                float a_[4], b_[4];
                #pragma unroll
                for (int i = 0; i < 4; i++) a_[i] = T[ss][4*ty + i];
                #pragma unroll
                for (int j = 0; j < 4; j++) b_[j] = T[ss][4*tx + j];
                #pragma unroll
                for (int i = 0; i < 4; i++)
                    #pragma unroll
                    for (int j = 0; j < 4; j++) acc[i][j] += a_[i] * b_[j];
            }
            __syncthreads();
        }
        #pragma unroll
        for (int i = 0; i < 4; i++)
            #pragma unroll
            for (int j = 0; j < 4; j++)
                g_Mm[bh*4096 + (4*ty + i)*64 + (4*tx + j)] = acc[i][j];
    } else {
        const int vb = bid - 16;
        const int plane = vb >> 5;
        const int s0 = (vb & 31) * 64;
        const float* __restrict__ src = (plane < 16)
            ? g_V  + (size_t)plane * SQ * DH
            : g_LV + (size_t)(plane - 16) * SQ * DH;
        #pragma unroll
        for (int t = 0; t < 16; t++) {
            int idx = tid + 256*t;
            int sl = idx >> 6, d = idx & 63;
            T[d][sl] = src[(size_t)(s0 + sl) * DH + d];
        }
        __syncthreads();
        uint2* dst = g_Vtp + (size_t)plane * DH * (SQ/2);
        #pragma unroll
        for (int t = 0; t < 8; t++) {
            int idx = tid + 256*t;
            int d = idx >> 5, sp = idx & 31;
            dst[(size_t)d * (SQ/2) + (s0 >> 1) + pidx(sp)] = pk_pair(T[d][2*sp], T[d][2*sp + 1]);
        }
    }
}

// ---------------- kernel 4: flash attention, depth-3 pipeline, inline LQ2 ----------------
__global__ __launch_bounds__(256, 1) void flash_bf(const float* __restrict__ mask,
                                                   float* __restrict__ out) {
    extern __shared__ uint4 smem4[];   // 3 stages x (K 1024 + V 1024) uint4 = 96KB

    const int rt = blockIdx.x;
    const int plane = blockIdx.y;
    const int branch = plane >> 4;
    const int cidx = plane & 15;
    const int bb = cidx >> 3;
    const int h  = cidx & 7;
    const int ho = branch ? (8 + h) : h;
    const bool domask = (branch == 0);

    const uint2* Kp  = g_Kp  + (size_t)plane * SQ * (DH/2);
    const uint2* Vtp = g_Vtp + (size_t)plane * DH * (SQ/2);

    const int tid  = threadIdx.x;
    const int lane = tid & 31;
    const int g    = lane >> 2;
    const int tg   = lane & 3;
    const int r0   = 16 * (tid >> 5);
    const int gx   = g & 1;

    const uint32_t sb = (uint32_t)__cvta_generic_to_shared(smem4);

    auto stage = [&](int kt) {
        int buf = kt % 3;
        uint32_t kb = sb + (uint32_t)buf * (2048u * 16u);
        uint32_t vb = kb + 1024u * 16u;
        #pragma unroll
        for (int t = 0; t < 4; t++) {
            int idx = tid + 256*t;          // 0..1023
            int r = idx >> 4, c = idx & 15;
            int sl = c ^ ((r & 1) << 2);
            cp16(kb + (uint32_t)(r*16 + sl)*16u,
                 Kp + (size_t)(kt*64 + r) * (DH/2) + 2*c);
            cp16(vb + (uint32_t)(r*16 + sl)*16u,
                 Vtp + (size_t)r * (SQ/2) + kt*32 + 2*c);
        }
        asm volatile("cp.async.commit_group;\n");
    };

    // ---- Q fragments (LOGICAL chunk indexing) ----
    uint32_t qh[4][4], ql[4][4];
    if (branch == 0) {
        const uint4* qb = (const uint4*)(g_Qp + (size_t)plane * SQ * (DH/2)
                                         + (size_t)(rt*128) * (DH/2));
        #pragma unroll
        for (int kk = 0; kk < 4; kk++) {
            uint4 u0 = qb[(size_t)(r0 + g    ) * 16 + 4*kk + tg];
            uint4 u1 = qb[(size_t)(r0 + g + 8) * 16 + 4*kk + tg];
            qh[kk][0] = u0.x; qh[kk][1] = u1.x; qh[kk][2] = u0.z; qh[kk][3] = u1.z;
            ql[kk][0] = u0.y; ql[kk][1] = u1.y; ql[kk][2] = u0.w; ql[kk][3] = u1.w;
        }
    } else {
        // inline LQ2 = (LQ @ G) * 0.125*log2e for this CTA's 128 rows
        float* Gs  = (float*)smem4;          // [64][65]
        float* LQs = Gs + 64*65;             // [128][65]
        const float* Gm = g_Mm + cidx * 4096;
        for (int i = tid; i < 4096; i += 256)
            Gs[(i >> 6)*65 + (i & 63)] = Gm[i];
        const float* LQr = g_LQ + ((size_t)cidx * SQ + (size_t)rt*128) * DH;
        for (int i = tid; i < 8192; i += 256)
            LQs[(i >> 6)*65 + (i & 63)] = LQr[i];
        __syncthreads();
        const float qsc = 0.125f * LOG2E;
        #pragma unroll
        for (int half = 0; half < 2; half++) {
            int r = r0 + g + 8*half;
            float a[16];
            #pragma unroll
            for (int i = 0; i < 16; i++) a[i] = 0.f;
            #pragma unroll 4
            for (int k = 0; k < 64; k++) {
                float lq = LQs[r*65 + k];
                const float* Gk = Gs + k*65 + 2*tg;
                #pragma unroll
                for (int kk = 0; kk < 4; kk++) {
                    a[4*kk+0] += lq * Gk[16*kk    ];
                    a[4*kk+1] += lq * Gk[16*kk + 1];
                    a[4*kk+2] += lq * Gk[16*kk + 8];
                    a[4*kk+3] += lq * Gk[16*kk + 9];
                }
            }
            #pragma unroll
            for (int kk = 0; kk < 4; kk++) {
                uint2 pA = pk_pair(a[4*kk+0]*qsc, a[4*kk+1]*qsc);
                uint2 pB = pk_pair(a[4*kk+2]*qsc, a[4*kk+3]*qsc);
                qh[kk][0 + half] = pA.x;  ql[kk][0 + half] = pA.y;
                qh[kk][2 + half] = pB.x;  ql[kk][2 + half] = pB.y;
            }
        }
        __syncthreads();   // done with scratch before pipeline reuses smem
    }

    float o[8][4];
    #pragma unroll
    for (int n = 0; n < 8; n++)
        #pragma unroll
        for (int q = 0; q < 4; q++) o[n][q] = 0.f;
    float m0r = -3.0e38f, m1r = -3.0e38f, l0r = 0.f, l1r = 0.f;

    stage(0); stage(1);

    for (int kt = 0; kt < 32; kt++) {
        if (kt < 31) asm volatile("cp.async.wait_group 1;\n");
        else         asm volatile("cp.async.wait_group 0;\n");
        __syncthreads();
        if (kt + 2 < 32) stage(kt + 2);

        const uint4* Ks = smem4 + (kt % 3) * 2048;
        const uint4* Vs = Ks + 1024;

        // mask loads early (independent of mma)
        float mk[8][2];
        if (domask) {
            #pragma unroll
            for (int n = 0; n < 8; n++) {
                float2 mm = __ldg((const float2*)&mask[(size_t)bb * SQ + kt*64 + 8*n + 2*tg]);
                mk[n][0] = mm.x * LOG2E; mk[n][1] = mm.y * LOG2E;
            }
        }

        // ---- S = Q K^T: register fragment = LOGICAL kk; smem slot = 4*kx+tg ----
        float sv[8][4];
        #pragma unroll
        for (int n = 0; n < 8; n++)
            #pragma unroll
            for (int q = 0; q < 4; q++) sv[n][q] = 0.f;

        #pragma unroll
        for (int kk = 0; kk < 4; kk++) {
            int kx = kk ^ gx;   // smem SLOT of logical chunk kk for rows with parity gx
            #pragma unroll
            for (int n = 0; n < 8; n++) {
                uint4 B = Ks[(8*n + g) * 16 + 4*kx + tg];
                mma16(sv[n], qh[kk], B.x, B.z);
                mma16(sv[n], qh[kk], B.y, B.w);
                mma16(sv[n], ql[kk], B.x, B.z);
            }
        }

        if (domask) {
            #pragma unroll
            for (int n = 0; n < 8; n++) {
                sv[n][0] += mk[n][0]; sv[n][1] += mk[n][1];
                sv[n][2] += mk[n][0]; sv[n][3] += mk[n][1];
            }
        }

        // ---- online softmax base-2 (rows g, g+8; 4-lane groups per row) ----
        float mt0 = sv[0][0], mt1 = sv[0][2];
        #pragma unroll
        for (int n = 0; n < 8; n++) {
            mt0 = fmaxf(mt0, fmaxf(sv[n][0], sv[n][1]));
            mt1 = fmaxf(mt1, fmaxf(sv[n][2], sv[n][3]));
        }
        mt0 = fmaxf(mt0, __shfl_xor_sync(0xffffffffu, mt0, 1));
        mt0 = fmaxf(mt0, __shfl_xor_sync(0xffffffffu, mt0, 2));
        mt1 = fmaxf(mt1, __shfl_xor_sync(0xffffffffu, mt1, 1));
        mt1 = fmaxf(mt1, __shfl_xor_sync(0xffffffffu, mt1, 2));

        float mn0 = fmaxf(m0r, mt0), mn1 = fmaxf(m1r, mt1);
        float c0 = ex2(m0r - mn0), c1 = ex2(m1r - mn1);
        float s0 = 0.f, s1 = 0.f;
        #pragma unroll
        for (int n = 0; n < 8; n++) {
            sv[n][0] = ex2(sv[n][0] - mn0); s0 += sv[n][0];
            sv[n][1] = ex2(sv[n][1] - mn0); s0 += sv[n][1];
            sv[n][2] = ex2(sv[n][2] - mn1); s1 += sv[n][2];
            sv[n][3] = ex2(sv[n][3] - mn1); s1 += sv[n][3];
        }
        s0 += __shfl_xor_sync(0xffffffffu, s0, 1);
        s0 += __shfl_xor_sync(0xffffffffu, s0, 2);
        s1 += __shfl_xor_sync(0xffffffffu, s1, 1);
        s1 += __shfl_xor_sync(0xffffffffu, s1, 2);
        l0r = l0r * c0 + s0; m0r = mn0;
        l1r = l1r * c1 + s1; m1r = mn1;
        #pragma unroll
        for (int n = 0; n < 8; n++) {
            o[n][0] *= c0; o[n][1] *= c0;
            o[n][2] *= c1; o[n][3] *= c1;
        }

        // ---- pack P into bf16 hi/lo A-fragments (pure local, LOGICAL index) ----
        uint32_t php[8][2], plp[8][2];
        #pragma unroll
        for (int n = 0; n < 8; n++) {
            __nv_bfloat16 h0 = __float2bfloat16_rn(sv[n][0]);
            __nv_bfloat16 h1 = __float2bfloat16_rn(sv[n][1]);
            __nv_bfloat16 h2 = __float2bfloat16_rn(sv[n][2]);
            __nv_bfloat16 h3 = __float2bfloat16_rn(sv[n][3]);
            php[n][0] = pk2(h0, h1);
            php[n][1] = pk2(h2, h3);
            float l0 = sv[n][0] - __bfloat162float(h0);
            float l1 = sv[n][1] - __bfloat162float(h1);
            float l2 = sv[n][2] - __bfloat162float(h2);
            float l3 = sv[n][3] - __bfloat162float(h3);
            plp[n][0] = pk2(__float2bfloat16_rn(l0), __float2bfloat16_rn(l1));
            plp[n][1] = pk2(__float2bfloat16_rn(l2), __float2bfloat16_rn(l3));
        }

        // ---- O += P V: A = LOGICAL chunk c; V smem slot = 4*cx+tg ----
        #pragma unroll
        for (int c = 0; c < 4; c++) {
            int cx = c ^ gx;
            uint32_t ah[4] = { php[2*c][0], php[2*c][1], php[2*c+1][0], php[2*c+1][1] };
            uint32_t al[4] = { plp[2*c][0], plp[2*c][1], plp[2*c+1][0], plp[2*c+1][1] };
            #pragma unroll
            for (int n = 0; n < 8; n++) {
                uint4 B = Vs[(8*n + g) * 16 + 4*cx + tg];
                mma16(o[n], ah, B.x, B.z);
                mma16(o[n], ah, B.y, B.w);
                mma16(o[n], al, B.x, B.z);
            }
        }
    }

    // ---- epilogue ----
    float inv0 = 1.0f / l0r, inv1 = 1.0f / l1r;
    int s0row = rt*128 + r0 + g;
    int s1row = s0row + 8;
    #pragma unroll
    for (int n = 0; n < 8; n++) {
        int col = 8*n + 2*tg;
        *(float2*)&out[(size_t)(bb * SQ + s0row) * HID + ho*64 + col] =
            make_float2(o[n][0] * inv0, o[n][1] * inv0);
        *(float2*)&out[(size_t)(bb * SQ + s1row) * HID + ho*64 + col] =
            make_float2(o[n][2] * inv1, o[n][3] * inv1);
    }
}

// ---------------- host ----------------
extern "C" void kernel_launch(void* const* d_in, const int* in_sizes, int n_in,
                              void* d_out, int out_size) {
    const float* X    = (const float*)d_in[0];
    const float* mask = (const float*)d_in[1];

    ProjW pw;
    pw.w[0] = (const float*)d_in[2];  pw.b[0] = (const float*)d_in[3];   // wq, bq
    pw.w[1] = (const float*)d_in[4];  pw.b[1] = (const float*)d_in[5];   // wk, bk
    pw.w[2] = (const float*)d_in[6];  pw.b[2] = (const float*)d_in[7];   // wv, bv
    pw.w[3] = (const float*)d_in[8];  pw.b[3] = (const float*)d_in[9];   // wlq
    pw.w[4] = (const float*)d_in[10]; pw.b[4] = (const float*)d_in[11];  // wlk1
    pw.w[5] = (const float*)d_in[12]; pw.b[5] = (const float*)d_in[13];  // wlk2
    pw.w[6] = (const float*)d_in[14]; pw.b[6] = (const float*)d_in[15];  // wlv1, blv1
    pw.w2   = (const float*)d_in[16]; pw.b2   = (const float*)d_in[17];  // wlv2, blv2

    prep_kernel<<<1921, 256>>>(X, pw);                                // 1

    const int psmem = 3 * 1536 * sizeof(uint4);                       // 73,728 B
    cudaFuncSetAttribute(proj_bf, cudaFuncAttributeMaxDynamicSharedMemorySize, psmem);
    proj_bf<<<dim3(8, 32, 7), 256, psmem>>>(pw);                      // 2

    aux_kernel<<<1040, 256>>>();                                      // 3 (gram + vtrans)

    const int fsmem = 3 * 2048 * sizeof(uint4);                       // 98,304 B
    cudaFuncSetAttribute(flash_bf, cudaFuncAttributeMaxDynamicSharedMemorySize, fsmem);
    flash_bf<<<dim3(16, 32), 256, fsmem>>>(mask, (float*)d_out);      // 4 (ncu slot)
}